// round 8
// baseline (speedup 1.0000x reference)
#include <cuda_runtime.h>
#include <math.h>

#define B_   2
#define S_   2048
#define D_   1024
#define H_   16
#define HD_  64
#define MS_  (B_*S_)        // 4096 rows
#define NQ_  (2*D_)         // 2048
#define PAD  68
#define LAMBDA_INIT 0.2f
#define SCALE_QK 0.125f     // 1/sqrt(64)

// ---------------- scratch ----------------
__device__ float g_q[MS_ * NQ_];
__device__ float g_k[MS_ * NQ_];
__device__ float g_v[MS_ * D_];
__device__ float g_y[MS_ * D_];
__device__ float g_lam[H_];

// ---------------- GEMM: C[M,N] = A[M,K] @ W[N,K]^T + bias[N] ----------------
__global__ void gemm_nt_bias(const float* __restrict__ A, const float* __restrict__ W,
                             const float* __restrict__ bias, float* __restrict__ C,
                             int M, int N, int K) {
    __shared__ float As[16 * 132];
    __shared__ float Ws[16 * 132];

    const int tid = threadIdx.x;
    const int tx = tid & 15;
    const int ty = tid >> 4;
    const int row0 = blockIdx.y * 128;
    const int col0 = blockIdx.x * 128;

    float acc[8][8];
#pragma unroll
    for (int i = 0; i < 8; i++)
#pragma unroll
        for (int j = 0; j < 8; j++) acc[i][j] = 0.f;

    for (int k0 = 0; k0 < K; k0 += 16) {
#pragma unroll
        for (int i = 0; i < 2; i++) {
            int idx = tid + i * 256;
            int r = idx >> 2;
            int c = (idx & 3) << 2;
            float4 av = *(const float4*)&A[(size_t)(row0 + r) * K + k0 + c];
            float4 wv = *(const float4*)&W[(size_t)(col0 + r) * K + k0 + c];
            As[(c + 0) * 132 + r] = av.x;
            As[(c + 1) * 132 + r] = av.y;
            As[(c + 2) * 132 + r] = av.z;
            As[(c + 3) * 132 + r] = av.w;
            Ws[(c + 0) * 132 + r] = wv.x;
            Ws[(c + 1) * 132 + r] = wv.y;
            Ws[(c + 2) * 132 + r] = wv.z;
            Ws[(c + 3) * 132 + r] = wv.w;
        }
        __syncthreads();
#pragma unroll
        for (int kk = 0; kk < 16; kk++) {
            float4 a0 = *(float4*)&As[kk * 132 + ty * 8];
            float4 a1 = *(float4*)&As[kk * 132 + ty * 8 + 4];
            float4 w0 = *(float4*)&Ws[kk * 132 + tx * 8];
            float4 w1 = *(float4*)&Ws[kk * 132 + tx * 8 + 4];
            float a[8] = {a0.x, a0.y, a0.z, a0.w, a1.x, a1.y, a1.z, a1.w};
            float w[8] = {w0.x, w0.y, w0.z, w0.w, w1.x, w1.y, w1.z, w1.w};
#pragma unroll
            for (int i = 0; i < 8; i++)
#pragma unroll
                for (int j = 0; j < 8; j++) acc[i][j] += a[i] * w[j];
        }
        __syncthreads();
    }

    float bj[8];
#pragma unroll
    for (int j = 0; j < 8; j++) bj[j] = bias[col0 + tx * 8 + j];
#pragma unroll
    for (int i = 0; i < 8; i++) {
        int row = row0 + ty * 8 + i;
#pragma unroll
        for (int j4 = 0; j4 < 2; j4++) {
            float4 v;
            v.x = acc[i][j4 * 4 + 0] + bj[j4 * 4 + 0];
            v.y = acc[i][j4 * 4 + 1] + bj[j4 * 4 + 1];
            v.z = acc[i][j4 * 4 + 2] + bj[j4 * 4 + 2];
            v.w = acc[i][j4 * 4 + 3] + bj[j4 * 4 + 3];
            *(float4*)&C[(size_t)row * N + col0 + tx * 8 + j4 * 4] = v;
        }
    }
}

// ---------------- RoPE in place on g_q, g_k — FLIPPED rotation (R6 result) ----
// [x1*c + x2*s, -x1*s + x2*c]
__global__ void rope_kernel() {
    const int r = blockIdx.x;
    const int h = threadIdx.x >> 5;
    const int d = threadIdx.x & 31;
    const int s = r & (S_ - 1);

    float invf = (float)pow(10000.0, -(double)d / 32.0);
    float angf = (float)s * invf;
    double cd, sd;
    sincos((double)angf, &cd, &sd);
    const float c = (float)cd, sn = -(float)sd;   // flipped sign

    const size_t base = (size_t)r * NQ_ + h * 128;
    {
        float x1 = g_q[base + d], x2 = g_q[base + d + 32];
        g_q[base + d]      = x1 * c - x2 * sn;
        g_q[base + d + 32] = x1 * sn + x2 * c;
    }
    {
        float x1 = g_q[base + 64 + d], x2 = g_q[base + 96 + d];
        g_q[base + 64 + d] = x1 * c - x2 * sn;
        g_q[base + 96 + d] = x1 * sn + x2 * c;
    }
    {
        float x1 = g_k[base + d], x2 = g_k[base + d + 32];
        g_k[base + d]      = x1 * c - x2 * sn;
        g_k[base + d + 32] = x1 * sn + x2 * c;
    }
    {
        float x1 = g_k[base + 64 + d], x2 = g_k[base + 96 + d];
        g_k[base + 64 + d] = x1 * c - x2 * sn;
        g_k[base + 96 + d] = x1 * sn + x2 * c;
    }
}

// ---------------- lambda ----------------
__global__ void lam_kernel(const float* __restrict__ lq1, const float* __restrict__ lk1,
                           const float* __restrict__ lq2, const float* __restrict__ lk2) {
    int h = threadIdx.x;
    if (h < H_) {
        float d1 = 0.f, d2 = 0.f;
        for (int i = 0; i < HD_; i++) {
            d1 += lq1[h * HD_ + i] * lk1[h * HD_ + i];
            d2 += lq2[h * HD_ + i] * lk2[h * HD_ + i];
        }
        g_lam[h] = LAMBDA_INIT + expf(d1) - expf(d2);
    }
}

// ---------------- dual-stream causal attention (plain exp) ----------------
__global__ void attn_kernel(const float* __restrict__ head_w) {
    extern __shared__ float sm[];
    float* sQ1 = sm;
    float* sQ2 = sQ1 + 64 * PAD;
    float* sK1 = sQ2 + 64 * PAD;
    float* sK2 = sK1 + 64 * PAD;
    float* sV  = sK2 + 64 * PAD;
    float* sP1 = sV  + 64 * PAD;
    float* sP2 = sP1 + 64 * PAD;
    float* sR1 = sP2 + 64 * PAD;
    float* sR2 = sR1 + 256;

    const int qt = blockIdx.x;
    const int h  = blockIdx.y;
    const int b  = blockIdx.z;
    const int tid = threadIdx.x;
    const int qr = tid >> 2;
    const int c4 = tid & 3;
    const int qidx = qt * 64 + qr;

#pragma unroll
    for (int i = 0; i < 4; i++) {
        int idx = tid + i * 256;
        int r = idx >> 4;
        int c = (idx & 15) << 2;
        const float* qrow = &g_q[(size_t)(b * S_ + qt * 64 + r) * NQ_ + h * 128];
        float4 v1 = *(const float4*)&qrow[c];
        float4 v2 = *(const float4*)&qrow[64 + c];
        v1.x *= SCALE_QK; v1.y *= SCALE_QK; v1.z *= SCALE_QK; v1.w *= SCALE_QK;
        v2.x *= SCALE_QK; v2.y *= SCALE_QK; v2.z *= SCALE_QK; v2.w *= SCALE_QK;
        *(float4*)&sQ1[r * PAD + c] = v1;
        *(float4*)&sQ2[r * PAD + c] = v2;
    }

    float acc1[16], acc2[16];
#pragma unroll
    for (int j = 0; j < 16; j++) { acc1[j] = 0.f; acc2[j] = 0.f; }
    float l1 = 0.f, l2 = 0.f;

    for (int kt = 0; kt <= qt; kt++) {
        __syncthreads();
#pragma unroll
        for (int i = 0; i < 4; i++) {
            int idx = tid + i * 256;
            int r = idx >> 4;
            int c = (idx & 15) << 2;
            const float* krow = &g_k[(size_t)(b * S_ + kt * 64 + r) * NQ_ + h * 128];
            *(float4*)&sK1[r * PAD + c] = *(const float4*)&krow[c];
            *(float4*)&sK2[r * PAD + c] = *(const float4*)&krow[64 + c];
            *(float4*)&sV[r * PAD + c] =
                *(const float4*)&g_v[(size_t)(b * S_ + kt * 64 + r) * D_ + h * 64 + c];
        }
        __syncthreads();

        float s1v[16], s2v[16];
#pragma unroll
        for (int j = 0; j < 16; j++) { s1v[j] = 0.f; s2v[j] = 0.f; }

#pragma unroll 4
        for (int kk4 = 0; kk4 < 16; kk4++) {
            float4 q1 = *(float4*)&sQ1[qr * PAD + kk4 * 4];
            float4 q2 = *(float4*)&sQ2[qr * PAD + kk4 * 4];
#pragma unroll
            for (int j = 0; j < 16; j++) {
                float4 k1 = *(float4*)&sK1[(c4 * 16 + j) * PAD + kk4 * 4];
                float4 k2 = *(float4*)&sK2[(c4 * 16 + j) * PAD + kk4 * 4];
                s1v[j] += q1.x * k1.x + q1.y * k1.y + q1.z * k1.z + q1.w * k1.w;
                s2v[j] += q2.x * k2.x + q2.y * k2.y + q2.z * k2.z + q2.w * k2.w;
            }
        }

        const int kbase = kt * 64 + c4 * 16;
        float ts1 = 0.f, ts2 = 0.f;
#pragma unroll
        for (int j = 0; j < 16; j++) {
            bool masked = (kbase + j > qidx);
            s1v[j] = masked ? 0.f : __expf(s1v[j]);
            s2v[j] = masked ? 0.f : __expf(s2v[j]);
            ts1 += s1v[j];
            ts2 += s2v[j];
        }
        sR1[tid] = ts1;
        sR2[tid] = ts2;

#pragma unroll
        for (int j4 = 0; j4 < 4; j4++) {
            *(float4*)&sP1[qr * PAD + c4 * 16 + j4 * 4] =
                make_float4(s1v[j4 * 4], s1v[j4 * 4 + 1], s1v[j4 * 4 + 2], s1v[j4 * 4 + 3]);
            *(float4*)&sP2[qr * PAD + c4 * 16 + j4 * 4] =
                make_float4(s2v[j4 * 4], s2v[j4 * 4 + 1], s2v[j4 * 4 + 2], s2v[j4 * 4 + 3]);
        }
        __syncthreads();

        l1 += sR1[qr * 4 + 0] + sR1[qr * 4 + 1] + sR1[qr * 4 + 2] + sR1[qr * 4 + 3];
        l2 += sR2[qr * 4 + 0] + sR2[qr * 4 + 1] + sR2[qr * 4 + 2] + sR2[qr * 4 + 3];

#pragma unroll 4
        for (int kc = 0; kc < 64; kc++) {
            float p1 = sP1[qr * PAD + kc];
            float p2 = sP2[qr * PAD + kc];
#pragma unroll
            for (int j4 = 0; j4 < 4; j4++) {
                float4 vv = *(float4*)&sV[kc * PAD + c4 * 16 + j4 * 4];
                acc1[j4 * 4 + 0] += p1 * vv.x;
                acc1[j4 * 4 + 1] += p1 * vv.y;
                acc1[j4 * 4 + 2] += p1 * vv.z;
                acc1[j4 * 4 + 3] += p1 * vv.w;
                acc2[j4 * 4 + 0] += p2 * vv.x;
                acc2[j4 * 4 + 1] += p2 * vv.y;
                acc2[j4 * 4 + 2] += p2 * vv.z;
                acc2[j4 * 4 + 3] += p2 * vv.w;
            }
        }
    }

    __syncthreads();
    float lam = g_lam[h];
    float inv1 = 1.f / l1, inv2 = 1.f / l2;
    float o[16];
    float ss = 0.f;
#pragma unroll
    for (int j = 0; j < 16; j++) {
        o[j] = acc1[j] * inv1 - lam * (acc2[j] * inv2);
        ss += o[j] * o[j];
    }
    sR1[tid] = ss;
    __syncthreads();
    ss = sR1[qr * 4 + 0] + sR1[qr * 4 + 1] + sR1[qr * 4 + 2] + sR1[qr * 4 + 3];
    float rn = rsqrtf(ss * (1.f / 64.f) + 1e-6f);

    size_t orow = (size_t)(b * S_ + qidx) * D_ + h * 64 + c4 * 16;
#pragma unroll
    for (int j4 = 0; j4 < 4; j4++) {
        float4 v;
        v.x = o[j4 * 4 + 0] * rn * head_w[h * 64 + c4 * 16 + j4 * 4 + 0] * 0.8f;
        v.y = o[j4 * 4 + 1] * rn * head_w[h * 64 + c4 * 16 + j4 * 4 + 1] * 0.8f;
        v.z = o[j4 * 4 + 2] * rn * head_w[h * 64 + c4 * 16 + j4 * 4 + 2] * 0.8f;
        v.w = o[j4 * 4 + 3] * rn * head_w[h * 64 + c4 * 16 + j4 * 4 + 3] * 0.8f;
        *(float4*)&g_y[orow + j4 * 4] = v;
    }
}

// ---------------- launch ----------------
extern "C" void kernel_launch(void* const* d_in, const int* in_sizes, int n_in,
                              void* d_out, int out_size) {
    const float* x   = (const float*)d_in[0];
    const float* Wq  = (const float*)d_in[1];
    const float* bq  = (const float*)d_in[2];
    const float* Wk  = (const float*)d_in[3];
    const float* bk  = (const float*)d_in[4];
    const float* Wv  = (const float*)d_in[5];
    const float* bv  = (const float*)d_in[6];
    const float* Wo  = (const float*)d_in[7];
    const float* bo  = (const float*)d_in[8];
    const float* hw  = (const float*)d_in[9];
    const float* lq1 = (const float*)d_in[10];
    const float* lk1 = (const float*)d_in[11];
    const float* lq2 = (const float*)d_in[12];
    const float* lk2 = (const float*)d_in[13];
    float* out = (float*)d_out;

    float *pq, *pk, *pv, *py;
    cudaGetSymbolAddress((void**)&pq, g_q);
    cudaGetSymbolAddress((void**)&pk, g_k);
    cudaGetSymbolAddress((void**)&pv, g_v);
    cudaGetSymbolAddress((void**)&py, g_y);

    const int smem_attn = (7 * 64 * PAD + 512) * (int)sizeof(float);
    cudaFuncSetAttribute(attn_kernel, cudaFuncAttributeMaxDynamicSharedMemorySize, smem_attn);

    dim3 blk(256);
    gemm_nt_bias<<<dim3(NQ_ / 128, MS_ / 128), blk>>>(x, Wq, bq, pq, MS_, NQ_, D_);
    gemm_nt_bias<<<dim3(NQ_ / 128, MS_ / 128), blk>>>(x, Wk, bk, pk, MS_, NQ_, D_);
    gemm_nt_bias<<<dim3(D_ / 128, MS_ / 128), blk>>>(x, Wv, bv, pv, MS_, D_, D_);
    rope_kernel<<<MS_, 512>>>();
    lam_kernel<<<1, 32>>>(lq1, lk1, lq2, lk2);
    attn_kernel<<<dim3(S_ / 64, H_, B_), blk, smem_attn>>>(hw);
    gemm_nt_bias<<<dim3(D_ / 128, MS_ / 128), blk>>>(py, Wo, bo, out, MS_, D_, D_);
}

// round 9
// speedup vs baseline: 1.5550x; 1.5550x over previous
#include <cuda_runtime.h>
#include <math.h>

#define B_   2
#define S_   2048
#define D_   1024
#define H_   16
#define HD_  64
#define MS_  (B_*S_)        // 4096 rows
#define NQ_  (2*D_)         // 2048
#define PAD  68
#define LAMBDA_INIT 0.2f
#define SCALE_QK 0.125f     // 1/sqrt(64)

// ---------------- scratch ----------------
__device__ float g_q[MS_ * NQ_];
__device__ float g_k[MS_ * NQ_];
__device__ float g_v[MS_ * D_];
__device__ float g_y[MS_ * D_];
__device__ float g_lam[H_];
__device__ float g_cos[S_ * 32];
__device__ float g_sin[S_ * 32];

// ---------------- RoPE table (exact same numerics as verified path) ----------------
__global__ void rope_table_kernel() {
    const int s = blockIdx.x;
    const int d = threadIdx.x;   // 0..31
    float invf = (float)pow(10000.0, -(double)d / 32.0);
    float angf = (float)s * invf;
    double cd, sd;
    sincos((double)angf, &cd, &sd);
    g_cos[s * 32 + d] = (float)cd;
    g_sin[s * 32 + d] = -(float)sd;   // flipped rotation (verified R6/R7)
}

// ---------------- RoPE apply, memory-bound ----------------
__global__ void rope_kernel() {
    const int r = blockIdx.x;
    const int h = threadIdx.x >> 5;
    const int d = threadIdx.x & 31;
    const int s = r & (S_ - 1);

    const float c  = g_cos[s * 32 + d];
    const float sn = g_sin[s * 32 + d];

    const size_t base = (size_t)r * NQ_ + h * 128;
    {
        float x1 = g_q[base + d], x2 = g_q[base + d + 32];
        g_q[base + d]      = x1 * c - x2 * sn;
        g_q[base + d + 32] = x1 * sn + x2 * c;
    }
    {
        float x1 = g_q[base + 64 + d], x2 = g_q[base + 96 + d];
        g_q[base + 64 + d] = x1 * c - x2 * sn;
        g_q[base + 96 + d] = x1 * sn + x2 * c;
    }
    {
        float x1 = g_k[base + d], x2 = g_k[base + d + 32];
        g_k[base + d]      = x1 * c - x2 * sn;
        g_k[base + d + 32] = x1 * sn + x2 * c;
    }
    {
        float x1 = g_k[base + 64 + d], x2 = g_k[base + 96 + d];
        g_k[base + 64 + d] = x1 * c - x2 * sn;
        g_k[base + 96 + d] = x1 * sn + x2 * c;
    }
}

// ---------------- GEMM: C = A @ W^T + bias, double-buffered ----------------
__global__ void gemm_nt_bias(const float* __restrict__ A, const float* __restrict__ W,
                             const float* __restrict__ bias, float* __restrict__ C,
                             int M, int N, int K) {
    __shared__ float As[2][16 * 132];
    __shared__ float Ws[2][16 * 132];

    const int tid = threadIdx.x;
    const int tx = tid & 15;
    const int ty = tid >> 4;
    const int row0 = blockIdx.y * 128;
    const int col0 = blockIdx.x * 128;

    const int r0 = tid >> 2;                 // 0..63
    const int r1 = r0 + 64;                  // 64..127
    const int cc = (tid & 3) << 2;           // 0,4,8,12

    float acc[8][8];
#pragma unroll
    for (int i = 0; i < 8; i++)
#pragma unroll
        for (int j = 0; j < 8; j++) acc[i][j] = 0.f;

    const int T = K / 16;

    // preload tile 0
    {
        float4 a0 = *(const float4*)&A[(size_t)(row0 + r0) * K + cc];
        float4 a1 = *(const float4*)&A[(size_t)(row0 + r1) * K + cc];
        float4 w0 = *(const float4*)&W[(size_t)(col0 + r0) * K + cc];
        float4 w1 = *(const float4*)&W[(size_t)(col0 + r1) * K + cc];
        As[0][(cc + 0) * 132 + r0] = a0.x; As[0][(cc + 1) * 132 + r0] = a0.y;
        As[0][(cc + 2) * 132 + r0] = a0.z; As[0][(cc + 3) * 132 + r0] = a0.w;
        As[0][(cc + 0) * 132 + r1] = a1.x; As[0][(cc + 1) * 132 + r1] = a1.y;
        As[0][(cc + 2) * 132 + r1] = a1.z; As[0][(cc + 3) * 132 + r1] = a1.w;
        Ws[0][(cc + 0) * 132 + r0] = w0.x; Ws[0][(cc + 1) * 132 + r0] = w0.y;
        Ws[0][(cc + 2) * 132 + r0] = w0.z; Ws[0][(cc + 3) * 132 + r0] = w0.w;
        Ws[0][(cc + 0) * 132 + r1] = w1.x; Ws[0][(cc + 1) * 132 + r1] = w1.y;
        Ws[0][(cc + 2) * 132 + r1] = w1.z; Ws[0][(cc + 3) * 132 + r1] = w1.w;
    }
    __syncthreads();

    for (int t = 0; t < T; t++) {
        const int cur = t & 1;
        float4 a0, a1, w0, w1;
        if (t + 1 < T) {
            const int k0 = (t + 1) * 16;
            a0 = *(const float4*)&A[(size_t)(row0 + r0) * K + k0 + cc];
            a1 = *(const float4*)&A[(size_t)(row0 + r1) * K + k0 + cc];
            w0 = *(const float4*)&W[(size_t)(col0 + r0) * K + k0 + cc];
            w1 = *(const float4*)&W[(size_t)(col0 + r1) * K + k0 + cc];
        }

#pragma unroll
        for (int kk = 0; kk < 16; kk++) {
            float4 x0 = *(float4*)&As[cur][kk * 132 + ty * 8];
            float4 x1 = *(float4*)&As[cur][kk * 132 + ty * 8 + 4];
            float4 y0 = *(float4*)&Ws[cur][kk * 132 + tx * 8];
            float4 y1 = *(float4*)&Ws[cur][kk * 132 + tx * 8 + 4];
            float a[8] = {x0.x, x0.y, x0.z, x0.w, x1.x, x1.y, x1.z, x1.w};
            float w[8] = {y0.x, y0.y, y0.z, y0.w, y1.x, y1.y, y1.z, y1.w};
#pragma unroll
            for (int i = 0; i < 8; i++)
#pragma unroll
                for (int j = 0; j < 8; j++) acc[i][j] += a[i] * w[j];
        }

        if (t + 1 < T) {
            const int nxt = 1 - cur;
            As[nxt][(cc + 0) * 132 + r0] = a0.x; As[nxt][(cc + 1) * 132 + r0] = a0.y;
            As[nxt][(cc + 2) * 132 + r0] = a0.z; As[nxt][(cc + 3) * 132 + r0] = a0.w;
            As[nxt][(cc + 0) * 132 + r1] = a1.x; As[nxt][(cc + 1) * 132 + r1] = a1.y;
            As[nxt][(cc + 2) * 132 + r1] = a1.z; As[nxt][(cc + 3) * 132 + r1] = a1.w;
            Ws[nxt][(cc + 0) * 132 + r0] = w0.x; Ws[nxt][(cc + 1) * 132 + r0] = w0.y;
            Ws[nxt][(cc + 2) * 132 + r0] = w0.z; Ws[nxt][(cc + 3) * 132 + r0] = w0.w;
            Ws[nxt][(cc + 0) * 132 + r1] = w1.x; Ws[nxt][(cc + 1) * 132 + r1] = w1.y;
            Ws[nxt][(cc + 2) * 132 + r1] = w1.z; Ws[nxt][(cc + 3) * 132 + r1] = w1.w;
            __syncthreads();
        }
    }

    float bj[8];
#pragma unroll
    for (int j = 0; j < 8; j++) bj[j] = bias[col0 + tx * 8 + j];
#pragma unroll
    for (int i = 0; i < 8; i++) {
        int row = row0 + ty * 8 + i;
#pragma unroll
        for (int j4 = 0; j4 < 2; j4++) {
            float4 v;
            v.x = acc[i][j4 * 4 + 0] + bj[j4 * 4 + 0];
            v.y = acc[i][j4 * 4 + 1] + bj[j4 * 4 + 1];
            v.z = acc[i][j4 * 4 + 2] + bj[j4 * 4 + 2];
            v.w = acc[i][j4 * 4 + 3] + bj[j4 * 4 + 3];
            *(float4*)&C[(size_t)row * N + col0 + tx * 8 + j4 * 4] = v;
        }
    }
}

// ---------------- lambda ----------------
__global__ void lam_kernel(const float* __restrict__ lq1, const float* __restrict__ lk1,
                           const float* __restrict__ lq2, const float* __restrict__ lk2) {
    int h = threadIdx.x;
    if (h < H_) {
        float d1 = 0.f, d2 = 0.f;
        for (int i = 0; i < HD_; i++) {
            d1 += lq1[h * HD_ + i] * lk1[h * HD_ + i];
            d2 += lq2[h * HD_ + i] * lk2[h * HD_ + i];
        }
        g_lam[h] = LAMBDA_INIT + expf(d1) - expf(d2);
    }
}

// ---------------- dual-stream causal attention, 128-row Q tile, 2 rows/thread ----
// grid (S/128, H, B), 256 threads. thread: rows qr, qr+64 (qr=tid>>2); cols (tid&3)*16.
__global__ void attn_kernel(const float* __restrict__ head_w) {
    extern __shared__ float sm[];
    float* sQ1 = sm;                    // 128*PAD
    float* sQ2 = sQ1 + 128 * PAD;       // 128*PAD
    float* sK1 = sQ2 + 128 * PAD;       // 64*PAD
    float* sK2 = sK1 + 64 * PAD;        // 64*PAD
    float* sV  = sK2 + 64 * PAD;        // 64*PAD
    float* sP1 = sV  + 64 * PAD;        // 128*PAD
    float* sP2 = sP1 + 128 * PAD;       // 128*PAD
    float* sR1 = sP2 + 128 * PAD;       // 512
    float* sR2 = sR1 + 512;             // 512

    const int qt = blockIdx.x;
    const int h  = blockIdx.y;
    const int b  = blockIdx.z;
    const int tid = threadIdx.x;
    const int qr = tid >> 2;            // 0..63
    const int c4 = tid & 3;
    const int rA = qr, rB = qr + 64;
    const int qidxA = qt * 128 + rA;
    const int qidxB = qt * 128 + rB;

    // load Q tile (128 rows, both streams, pre-scaled)
#pragma unroll
    for (int i = 0; i < 8; i++) {
        int idx = tid + i * 256;
        int r = idx >> 4;                 // 0..127
        int c = (idx & 15) << 2;
        const float* qrow = &g_q[(size_t)(b * S_ + qt * 128 + r) * NQ_ + h * 128];
        float4 v1 = *(const float4*)&qrow[c];
        float4 v2 = *(const float4*)&qrow[64 + c];
        v1.x *= SCALE_QK; v1.y *= SCALE_QK; v1.z *= SCALE_QK; v1.w *= SCALE_QK;
        v2.x *= SCALE_QK; v2.y *= SCALE_QK; v2.z *= SCALE_QK; v2.w *= SCALE_QK;
        *(float4*)&sQ1[r * PAD + c] = v1;
        *(float4*)&sQ2[r * PAD + c] = v2;
    }

    float a1A[16], a2A[16], a1B[16], a2B[16];
#pragma unroll
    for (int j = 0; j < 16; j++) { a1A[j] = 0.f; a2A[j] = 0.f; a1B[j] = 0.f; a2B[j] = 0.f; }
    float l1A = 0.f, l2A = 0.f, l1B = 0.f, l2B = 0.f;

    const int ktmax = 2 * qt + 1;   // row B's last tile; row A masked there
    for (int kt = 0; kt <= ktmax; kt++) {
        __syncthreads();
#pragma unroll
        for (int i = 0; i < 4; i++) {
            int idx = tid + i * 256;
            int r = idx >> 4;             // 0..63
            int c = (idx & 15) << 2;
            const float* krow = &g_k[(size_t)(b * S_ + kt * 64 + r) * NQ_ + h * 128];
            *(float4*)&sK1[r * PAD + c] = *(const float4*)&krow[c];
            *(float4*)&sK2[r * PAD + c] = *(const float4*)&krow[64 + c];
            *(float4*)&sV[r * PAD + c] =
                *(const float4*)&g_v[(size_t)(b * S_ + kt * 64 + r) * D_ + h * 64 + c];
        }
        __syncthreads();

        float s1A[16], s2A[16], s1B[16], s2B[16];
#pragma unroll
        for (int j = 0; j < 16; j++) { s1A[j] = 0.f; s2A[j] = 0.f; s1B[j] = 0.f; s2B[j] = 0.f; }

#pragma unroll 4
        for (int kk4 = 0; kk4 < 16; kk4++) {
            float4 q1A = *(float4*)&sQ1[rA * PAD + kk4 * 4];
            float4 q2A = *(float4*)&sQ2[rA * PAD + kk4 * 4];
            float4 q1B = *(float4*)&sQ1[rB * PAD + kk4 * 4];
            float4 q2B = *(float4*)&sQ2[rB * PAD + kk4 * 4];
#pragma unroll
            for (int j = 0; j < 16; j++) {
                float4 k1 = *(float4*)&sK1[(c4 * 16 + j) * PAD + kk4 * 4];
                float4 k2 = *(float4*)&sK2[(c4 * 16 + j) * PAD + kk4 * 4];
                s1A[j] += q1A.x * k1.x + q1A.y * k1.y + q1A.z * k1.z + q1A.w * k1.w;
                s2A[j] += q2A.x * k2.x + q2A.y * k2.y + q2A.z * k2.z + q2A.w * k2.w;
                s1B[j] += q1B.x * k1.x + q1B.y * k1.y + q1B.z * k1.z + q1B.w * k1.w;
                s2B[j] += q2B.x * k2.x + q2B.y * k2.y + q2B.z * k2.z + q2B.w * k2.w;
            }
        }

        const int kbase = kt * 64 + c4 * 16;
        float t1A = 0.f, t2A = 0.f, t1B = 0.f, t2B = 0.f;
#pragma unroll
        for (int j = 0; j < 16; j++) {
            bool mA = (kbase + j > qidxA);
            bool mB = (kbase + j > qidxB);
            s1A[j] = mA ? 0.f : __expf(s1A[j]);
            s2A[j] = mA ? 0.f : __expf(s2A[j]);
            s1B[j] = mB ? 0.f : __expf(s1B[j]);
            s2B[j] = mB ? 0.f : __expf(s2B[j]);
            t1A += s1A[j]; t2A += s2A[j];
            t1B += s1B[j]; t2B += s2B[j];
        }
        sR1[rA * 4 + c4] = t1A; sR2[rA * 4 + c4] = t2A;
        sR1[rB * 4 + c4] = t1B; sR2[rB * 4 + c4] = t2B;

#pragma unroll
        for (int j4 = 0; j4 < 4; j4++) {
            *(float4*)&sP1[rA * PAD + c4 * 16 + j4 * 4] =
                make_float4(s1A[j4 * 4], s1A[j4 * 4 + 1], s1A[j4 * 4 + 2], s1A[j4 * 4 + 3]);
            *(float4*)&sP2[rA * PAD + c4 * 16 + j4 * 4] =
                make_float4(s2A[j4 * 4], s2A[j4 * 4 + 1], s2A[j4 * 4 + 2], s2A[j4 * 4 + 3]);
            *(float4*)&sP1[rB * PAD + c4 * 16 + j4 * 4] =
                make_float4(s1B[j4 * 4], s1B[j4 * 4 + 1], s1B[j4 * 4 + 2], s1B[j4 * 4 + 3]);
            *(float4*)&sP2[rB * PAD + c4 * 16 + j4 * 4] =
                make_float4(s2B[j4 * 4], s2B[j4 * 4 + 1], s2B[j4 * 4 + 2], s2B[j4 * 4 + 3]);
        }
        __syncthreads();

        l1A += sR1[rA * 4 + 0] + sR1[rA * 4 + 1] + sR1[rA * 4 + 2] + sR1[rA * 4 + 3];
        l2A += sR2[rA * 4 + 0] + sR2[rA * 4 + 1] + sR2[rA * 4 + 2] + sR2[rA * 4 + 3];
        l1B += sR1[rB * 4 + 0] + sR1[rB * 4 + 1] + sR1[rB * 4 + 2] + sR1[rB * 4 + 3];
        l2B += sR2[rB * 4 + 0] + sR2[rB * 4 + 1] + sR2[rB * 4 + 2] + sR2[rB * 4 + 3];

#pragma unroll 2
        for (int kc = 0; kc < 64; kc++) {
            float p1A = sP1[rA * PAD + kc];
            float p2A = sP2[rA * PAD + kc];
            float p1B = sP1[rB * PAD + kc];
            float p2B = sP2[rB * PAD + kc];
#pragma unroll
            for (int j4 = 0; j4 < 4; j4++) {
                float4 vv = *(float4*)&sV[kc * PAD + c4 * 16 + j4 * 4];
                a1A[j4 * 4 + 0] += p1A * vv.x; a1A[j4 * 4 + 1] += p1A * vv.y;
                a1A[j4 * 4 + 2] += p1A * vv.z; a1A[j4 * 4 + 3] += p1A * vv.w;
                a2A[j4 * 4 + 0] += p2A * vv.x; a2A[j4 * 4 + 1] += p2A * vv.y;
                a2A[j4 * 4 + 2] += p2A * vv.z; a2A[j4 * 4 + 3] += p2A * vv.w;
                a1B[j4 * 4 + 0] += p1B * vv.x; a1B[j4 * 4 + 1] += p1B * vv.y;
                a1B[j4 * 4 + 2] += p1B * vv.z; a1B[j4 * 4 + 3] += p1B * vv.w;
                a2B[j4 * 4 + 0] += p2B * vv.x; a2B[j4 * 4 + 1] += p2B * vv.y;
                a2B[j4 * 4 + 2] += p2B * vv.z; a2B[j4 * 4 + 3] += p2B * vv.w;
            }
        }
    }

    // epilogue for both rows
    __syncthreads();
    const float lam = g_lam[h];
    const float hw0 = head_w[h * 64 + c4 * 16 + 0];  // loaded per element below anyway
    (void)hw0;
    float oA[16], oB[16];
    float ssA = 0.f, ssB = 0.f;
    {
        float i1 = 1.f / l1A, i2 = 1.f / l2A;
#pragma unroll
        for (int j = 0; j < 16; j++) {
            oA[j] = a1A[j] * i1 - lam * (a2A[j] * i2);
            ssA += oA[j] * oA[j];
        }
        i1 = 1.f / l1B; i2 = 1.f / l2B;
#pragma unroll
        for (int j = 0; j < 16; j++) {
            oB[j] = a1B[j] * i1 - lam * (a2B[j] * i2);
            ssB += oB[j] * oB[j];
        }
    }
    sR1[rA * 4 + c4] = ssA;
    sR1[rB * 4 + c4] = ssB;
    __syncthreads();
    ssA = sR1[rA * 4 + 0] + sR1[rA * 4 + 1] + sR1[rA * 4 + 2] + sR1[rA * 4 + 3];
    ssB = sR1[rB * 4 + 0] + sR1[rB * 4 + 1] + sR1[rB * 4 + 2] + sR1[rB * 4 + 3];
    const float rnA = rsqrtf(ssA * (1.f / 64.f) + 1e-6f);
    const float rnB = rsqrtf(ssB * (1.f / 64.f) + 1e-6f);

    const size_t oArow = (size_t)(b * S_ + qidxA) * D_ + h * 64 + c4 * 16;
    const size_t oBrow = (size_t)(b * S_ + qidxB) * D_ + h * 64 + c4 * 16;
#pragma unroll
    for (int j4 = 0; j4 < 4; j4++) {
        float4 vA, vB;
        const float* hwp = &head_w[h * 64 + c4 * 16 + j4 * 4];
        vA.x = oA[j4 * 4 + 0] * rnA * hwp[0] * 0.8f;
        vA.y = oA[j4 * 4 + 1] * rnA * hwp[1] * 0.8f;
        vA.z = oA[j4 * 4 + 2] * rnA * hwp[2] * 0.8f;
        vA.w = oA[j4 * 4 + 3] * rnA * hwp[3] * 0.8f;
        vB.x = oB[j4 * 4 + 0] * rnB * hwp[0] * 0.8f;
        vB.y = oB[j4 * 4 + 1] * rnB * hwp[1] * 0.8f;
        vB.z = oB[j4 * 4 + 2] * rnB * hwp[2] * 0.8f;
        vB.w = oB[j4 * 4 + 3] * rnB * hwp[3] * 0.8f;
        *(float4*)&g_y[oArow + j4 * 4] = vA;
        *(float4*)&g_y[oBrow + j4 * 4] = vB;
    }
}

// ---------------- launch ----------------
extern "C" void kernel_launch(void* const* d_in, const int* in_sizes, int n_in,
                              void* d_out, int out_size) {
    const float* x   = (const float*)d_in[0];
    const float* Wq  = (const float*)d_in[1];
    const float* bq  = (const float*)d_in[2];
    const float* Wk  = (const float*)d_in[3];
    const float* bk  = (const float*)d_in[4];
    const float* Wv  = (const float*)d_in[5];
    const float* bv  = (const float*)d_in[6];
    const float* Wo  = (const float*)d_in[7];
    const float* bo  = (const float*)d_in[8];
    const float* hw  = (const float*)d_in[9];
    const float* lq1 = (const float*)d_in[10];
    const float* lk1 = (const float*)d_in[11];
    const float* lq2 = (const float*)d_in[12];
    const float* lk2 = (const float*)d_in[13];
    float* out = (float*)d_out;

    float *pq, *pk, *pv, *py;
    cudaGetSymbolAddress((void**)&pq, g_q);
    cudaGetSymbolAddress((void**)&pk, g_k);
    cudaGetSymbolAddress((void**)&pv, g_v);
    cudaGetSymbolAddress((void**)&py, g_y);

    const int smem_attn = (128 * PAD * 4 + 64 * PAD * 3 + 1024) * (int)sizeof(float);
    cudaFuncSetAttribute(attn_kernel, cudaFuncAttributeMaxDynamicSharedMemorySize, smem_attn);

    dim3 blk(256);
    rope_table_kernel<<<S_, 32>>>();
    gemm_nt_bias<<<dim3(NQ_ / 128, MS_ / 128), blk>>>(x, Wq, bq, pq, MS_, NQ_, D_);
    gemm_nt_bias<<<dim3(NQ_ / 128, MS_ / 128), blk>>>(x, Wk, bk, pk, MS_, NQ_, D_);
    gemm_nt_bias<<<dim3(D_ / 128, MS_ / 128), blk>>>(x, Wv, bv, pv, MS_, D_, D_);
    rope_kernel<<<MS_, 512>>>();
    lam_kernel<<<1, 32>>>(lq1, lk1, lq2, lk2);
    attn_kernel<<<dim3(S_ / 128, H_, B_), blk, smem_attn>>>(hw);
    gemm_nt_bias<<<dim3(D_ / 128, MS_ / 128), blk>>>(py, Wo, bo, out, MS_, D_, D_);
}

// round 13
// speedup vs baseline: 4.3697x; 2.8101x over previous
#include <cuda_runtime.h>
#include <math.h>
#include <stdint.h>

#define B_   2
#define S_   2048
#define D_   1024
#define H_   16
#define MS_  (B_*S_)        // 4096 rows
#define NQ_  (2*D_)         // 2048
#define PAD  68             // gemm fp32 pad
#define QST  68             // attn Q/K/P row stride (floats)
#define VST  72             // attn V row stride (floats)
#define LAMBDA_INIT 0.2f
#define SCALE_QK 0.125f

// ---------------- scratch ----------------
__device__ float g_q[MS_ * NQ_];
__device__ float g_k[MS_ * NQ_];
__device__ float g_v[MS_ * D_];
__device__ float g_y[MS_ * D_];
__device__ float g_lam[H_];
__device__ float g_cos[S_ * 32];
__device__ float g_sin[S_ * 32];

// ---------------- helpers ----------------
__device__ __forceinline__ float to_tf32(float x) {
    uint32_t u;
    asm("cvt.rna.tf32.f32 %0, %1;\n" : "=r"(u) : "f"(x));
    return __uint_as_float(u);
}
__device__ __forceinline__ void mma_tf32(float* d, float a0, float a1, float a2, float a3,
                                         float b0, float b1) {
    asm volatile("mma.sync.aligned.m16n8k8.row.col.f32.tf32.tf32.f32 "
                 "{%0,%1,%2,%3},{%4,%5,%6,%7},{%8,%9},{%0,%1,%2,%3};\n"
                 : "+f"(d[0]), "+f"(d[1]), "+f"(d[2]), "+f"(d[3])
                 : "r"(__float_as_uint(a0)), "r"(__float_as_uint(a1)),
                   "r"(__float_as_uint(a2)), "r"(__float_as_uint(a3)),
                   "r"(__float_as_uint(b0)), "r"(__float_as_uint(b1)));
}

// ---------------- RoPE table ----------------
__global__ void rope_table_kernel() {
    const int s = blockIdx.x;
    const int d = threadIdx.x;
    float invf = (float)pow(10000.0, -(double)d / 32.0);
    float angf = (float)s * invf;
    double cd, sd;
    sincos((double)angf, &cd, &sd);
    g_cos[s * 32 + d] = (float)cd;
    g_sin[s * 32 + d] = -(float)sd;   // flipped rotation (verified)
}

// ---------------- RoPE apply, fp32 in place ----------------
__global__ void rope_kernel() {
    const int r = blockIdx.x;
    const int h = threadIdx.x >> 5;
    const int d = threadIdx.x & 31;
    const int s = r & (S_ - 1);
    const float c  = g_cos[s * 32 + d];
    const float sn = g_sin[s * 32 + d];
    const size_t base = (size_t)r * NQ_ + h * 128;
    {
        float x1 = g_q[base + d], x2 = g_q[base + d + 32];
        g_q[base + d]      = x1 * c - x2 * sn;
        g_q[base + d + 32] = x1 * sn + x2 * c;
    }
    {
        float x1 = g_q[base + 64 + d], x2 = g_q[base + 96 + d];
        g_q[base + 64 + d] = x1 * c - x2 * sn;
        g_q[base + 96 + d] = x1 * sn + x2 * c;
    }
    {
        float x1 = g_k[base + d], x2 = g_k[base + d + 32];
        g_k[base + d]      = x1 * c - x2 * sn;
        g_k[base + d + 32] = x1 * sn + x2 * c;
    }
    {
        float x1 = g_k[base + 64 + d], x2 = g_k[base + 96 + d];
        g_k[base + 64 + d] = x1 * c - x2 * sn;
        g_k[base + 96 + d] = x1 * sn + x2 * c;
    }
}

// ---------------- GEMM (R9, passing) ----------------
__global__ void gemm_nt_bias(const float* __restrict__ A, const float* __restrict__ W,
                             const float* __restrict__ bias, float* __restrict__ C,
                             int M, int N, int K) {
    __shared__ float As[2][16 * 132];
    __shared__ float Ws[2][16 * 132];
    const int tid = threadIdx.x;
    const int tx = tid & 15;
    const int ty = tid >> 4;
    const int row0 = blockIdx.y * 128;
    const int col0 = blockIdx.x * 128;
    const int r0 = tid >> 2;
    const int r1 = r0 + 64;
    const int cc = (tid & 3) << 2;

    float acc[8][8];
#pragma unroll
    for (int i = 0; i < 8; i++)
#pragma unroll
        for (int j = 0; j < 8; j++) acc[i][j] = 0.f;

    const int T = K / 16;
    {
        float4 a0 = *(const float4*)&A[(size_t)(row0 + r0) * K + cc];
        float4 a1 = *(const float4*)&A[(size_t)(row0 + r1) * K + cc];
        float4 w0 = *(const float4*)&W[(size_t)(col0 + r0) * K + cc];
        float4 w1 = *(const float4*)&W[(size_t)(col0 + r1) * K + cc];
        As[0][(cc + 0) * 132 + r0] = a0.x; As[0][(cc + 1) * 132 + r0] = a0.y;
        As[0][(cc + 2) * 132 + r0] = a0.z; As[0][(cc + 3) * 132 + r0] = a0.w;
        As[0][(cc + 0) * 132 + r1] = a1.x; As[0][(cc + 1) * 132 + r1] = a1.y;
        As[0][(cc + 2) * 132 + r1] = a1.z; As[0][(cc + 3) * 132 + r1] = a1.w;
        Ws[0][(cc + 0) * 132 + r0] = w0.x; Ws[0][(cc + 1) * 132 + r0] = w0.y;
        Ws[0][(cc + 2) * 132 + r0] = w0.z; Ws[0][(cc + 3) * 132 + r0] = w0.w;
        Ws[0][(cc + 0) * 132 + r1] = w1.x; Ws[0][(cc + 1) * 132 + r1] = w1.y;
        Ws[0][(cc + 2) * 132 + r1] = w1.z; Ws[0][(cc + 3) * 132 + r1] = w1.w;
    }
    __syncthreads();

    for (int t = 0; t < T; t++) {
        const int cur = t & 1;
        float4 a0, a1, w0, w1;
        if (t + 1 < T) {
            const int k0 = (t + 1) * 16;
            a0 = *(const float4*)&A[(size_t)(row0 + r0) * K + k0 + cc];
            a1 = *(const float4*)&A[(size_t)(row0 + r1) * K + k0 + cc];
            w0 = *(const float4*)&W[(size_t)(col0 + r0) * K + k0 + cc];
            w1 = *(const float4*)&W[(size_t)(col0 + r1) * K + k0 + cc];
        }
#pragma unroll
        for (int kk = 0; kk < 16; kk++) {
            float4 x0 = *(float4*)&As[cur][kk * 132 + ty * 8];
            float4 x1 = *(float4*)&As[cur][kk * 132 + ty * 8 + 4];
            float4 y0 = *(float4*)&Ws[cur][kk * 132 + tx * 8];
            float4 y1 = *(float4*)&Ws[cur][kk * 132 + tx * 8 + 4];
            float a[8] = {x0.x, x0.y, x0.z, x0.w, x1.x, x1.y, x1.z, x1.w};
            float w[8] = {y0.x, y0.y, y0.z, y0.w, y1.x, y1.y, y1.z, y1.w};
#pragma unroll
            for (int i = 0; i < 8; i++)
#pragma unroll
                for (int j = 0; j < 8; j++) acc[i][j] += a[i] * w[j];
        }
        if (t + 1 < T) {
            const int nxt = 1 - cur;
            As[nxt][(cc + 0) * 132 + r0] = a0.x; As[nxt][(cc + 1) * 132 + r0] = a0.y;
            As[nxt][(cc + 2) * 132 + r0] = a0.z; As[nxt][(cc + 3) * 132 + r0] = a0.w;
            As[nxt][(cc + 0) * 132 + r1] = a1.x; As[nxt][(cc + 1) * 132 + r1] = a1.y;
            As[nxt][(cc + 2) * 132 + r1] = a1.z; As[nxt][(cc + 3) * 132 + r1] = a1.w;
            Ws[nxt][(cc + 0) * 132 + r0] = w0.x; Ws[nxt][(cc + 1) * 132 + r0] = w0.y;
            Ws[nxt][(cc + 2) * 132 + r0] = w0.z; Ws[nxt][(cc + 3) * 132 + r0] = w0.w;
            Ws[nxt][(cc + 0) * 132 + r1] = w1.x; Ws[nxt][(cc + 1) * 132 + r1] = w1.y;
            Ws[nxt][(cc + 2) * 132 + r1] = w1.z; Ws[nxt][(cc + 3) * 132 + r1] = w1.w;
            __syncthreads();
        }
    }

    float bj[8];
#pragma unroll
    for (int j = 0; j < 8; j++) bj[j] = bias[col0 + tx * 8 + j];
#pragma unroll
    for (int i = 0; i < 8; i++) {
        int row = row0 + ty * 8 + i;
#pragma unroll
        for (int j4 = 0; j4 < 2; j4++) {
            float4 v;
            v.x = acc[i][j4 * 4 + 0] + bj[j4 * 4 + 0];
            v.y = acc[i][j4 * 4 + 1] + bj[j4 * 4 + 1];
            v.z = acc[i][j4 * 4 + 2] + bj[j4 * 4 + 2];
            v.w = acc[i][j4 * 4 + 3] + bj[j4 * 4 + 3];
            *(float4*)&C[(size_t)row * N + col0 + tx * 8 + j4 * 4] = v;
        }
    }
}

// ---------------- lambda ----------------
__global__ void lam_kernel(const float* __restrict__ lq1, const float* __restrict__ lk1,
                           const float* __restrict__ lq2, const float* __restrict__ lk2) {
    int h = threadIdx.x;
    if (h < H_) {
        float d1 = 0.f, d2 = 0.f;
        for (int i = 0; i < 64; i++) {
            d1 += lq1[h * 64 + i] * lk1[h * 64 + i];
            d2 += lq2[h * 64 + i] * lk2[h * 64 + i];
        }
        g_lam[h] = LAMBDA_INIT + expf(d1) - expf(d2);
    }
}

// ---------------- TF32 tensor-core dual-stream causal attention ----------------
// grid (16, H, B), 256 thr (8 warps). Block p does q-tiles {p, 31-p} (33 k-tiles).
// warps 0-3: stream 1, warps 4-7: stream 2; per warp 16 q-rows.
__global__ __launch_bounds__(256, 1) void attn_kernel(const float* __restrict__ head_w) {
    extern __shared__ __align__(16) float smem[];
    float* sQ1 = smem;                  // 64*QST
    float* sQ2 = sQ1 + 64 * QST;
    float* sK1 = sQ2 + 64 * QST;
    float* sK2 = sK1 + 64 * QST;
    float* sP1 = sK2 + 64 * QST;
    float* sP2 = sP1 + 64 * QST;
    float* sV  = sP2 + 64 * QST;        // 64*VST
    float* scratch = sK1;               // epilogue: 64 x 66 fp32, fits sK1

    const int p = blockIdx.x, h = blockIdx.y, b = blockIdx.z;
    const int tid = threadIdx.x;
    const int w = tid >> 5, lane = tid & 31;
    const int st = w >> 2, wr = w & 3;
    const int g = lane >> 2, tig = lane & 3;
    const float lam = g_lam[h];

    float* sQ  = st ? sQ2 : sQ1;
    float* sKs = st ? sK2 : sK1;
    float* sP  = st ? sP2 : sP1;
    const int rAl = 16 * wr + g;

    for (int rep = 0; rep < 2; rep++) {
        const int qt = (rep == 0) ? p : (31 - p);

        // load Q tile (both streams), tf32-rounded, pre-scaled
#pragma unroll
        for (int i = 0; i < 8; i++) {
            int idx = tid + i * 256;
            int strm = idx >> 10;
            int r = (idx >> 4) & 63;
            int c4 = idx & 15;
            float4 v = *(const float4*)&g_q[(size_t)(b * S_ + qt * 64 + r) * NQ_ + h * 128 + strm * 64 + c4 * 4];
            float* dst = (strm ? sQ2 : sQ1) + r * QST + c4 * 4;
            dst[0] = to_tf32(v.x * SCALE_QK);
            dst[1] = to_tf32(v.y * SCALE_QK);
            dst[2] = to_tf32(v.z * SCALE_QK);
            dst[3] = to_tf32(v.w * SCALE_QK);
        }

        float o[8][4];
#pragma unroll
        for (int n = 0; n < 8; n++) { o[n][0] = o[n][1] = o[n][2] = o[n][3] = 0.f; }
        float lA = 0.f, lB = 0.f;

        for (int kt = 0; kt <= qt; kt++) {
            __syncthreads();
            // load K1,K2,V tiles (tf32-rounded)
#pragma unroll
            for (int i = 0; i < 12; i++) {
                int idx = tid + i * 256;
                if (idx < 2048) {
                    int strm = idx >> 10;
                    int r = (idx >> 4) & 63;
                    int c4 = idx & 15;
                    float4 v = *(const float4*)&g_k[(size_t)(b * S_ + kt * 64 + r) * NQ_ + h * 128 + strm * 64 + c4 * 4];
                    float* dst = (strm ? sK2 : sK1) + r * QST + c4 * 4;
                    dst[0] = to_tf32(v.x); dst[1] = to_tf32(v.y);
                    dst[2] = to_tf32(v.z); dst[3] = to_tf32(v.w);
                } else {
                    int j = idx - 2048;
                    int r = j >> 4;
                    int c4 = j & 15;
                    float4 v = *(const float4*)&g_v[(size_t)(b * S_ + kt * 64 + r) * D_ + h * 64 + c4 * 4];
                    float* dst = sV + r * VST + c4 * 4;
                    dst[0] = to_tf32(v.x); dst[1] = to_tf32(v.y);
                    dst[2] = to_tf32(v.z); dst[3] = to_tf32(v.w);
                }
            }
            __syncthreads();

            // ---- S = Q·K^T ----
            float s[8][4];
#pragma unroll
            for (int n = 0; n < 8; n++) { s[n][0] = s[n][1] = s[n][2] = s[n][3] = 0.f; }
            const float* Qb = sQ + rAl * QST + tig;
            const float* Kb = sKs + g * QST + tig;
#pragma unroll
            for (int k8 = 0; k8 < 8; k8++) {
                const int ko = 8 * k8;
                float a0 = Qb[ko];
                float a1 = Qb[8 * QST + ko];
                float a2 = Qb[ko + 4];
                float a3 = Qb[8 * QST + ko + 4];
#pragma unroll
                for (int np = 0; np < 8; np++) {
                    float b0 = Kb[np * 8 * QST + ko];
                    float b1 = Kb[np * 8 * QST + ko + 4];
                    mma_tf32(s[np], a0, a1, a2, a3, b0, b1);
                }
            }

            // ---- mask + exp + row sums + store P ----
            const bool diag = (kt == qt);
            float sumA = 0.f, sumB = 0.f;
#pragma unroll
            for (int n = 0; n < 8; n++) {
                int c0 = 8 * n + 2 * tig;
                float p00, p01, p10, p11;
                if (diag) {
                    p00 = (c0     > rAl)     ? 0.f : __expf(s[n][0]);
                    p01 = (c0 + 1 > rAl)     ? 0.f : __expf(s[n][1]);
                    p10 = (c0     > rAl + 8) ? 0.f : __expf(s[n][2]);
                    p11 = (c0 + 1 > rAl + 8) ? 0.f : __expf(s[n][3]);
                } else {
                    p00 = __expf(s[n][0]); p01 = __expf(s[n][1]);
                    p10 = __expf(s[n][2]); p11 = __expf(s[n][3]);
                }
                sumA += p00 + p01;
                sumB += p10 + p11;
                *(float2*)&sP[rAl * QST + c0]       = make_float2(to_tf32(p00), to_tf32(p01));
                *(float2*)&sP[(rAl + 8) * QST + c0] = make_float2(to_tf32(p10), to_tf32(p11));
            }
            sumA += __shfl_xor_sync(0xffffffffu, sumA, 1);
            sumA += __shfl_xor_sync(0xffffffffu, sumA, 2);
            sumB += __shfl_xor_sync(0xffffffffu, sumB, 1);
            sumB += __shfl_xor_sync(0xffffffffu, sumB, 2);
            lA += sumA;
            lB += sumB;
            __syncwarp();

            // ---- O += P·V ----
            const float* Pb = sP + rAl * QST + tig;
#pragma unroll
            for (int k8 = 0; k8 < 8; k8++) {
                const int ko = 8 * k8;
                float a0 = Pb[ko];
                float a1 = Pb[8 * QST + ko];
                float a2 = Pb[ko + 4];
                float a3 = Pb[8 * QST + ko + 4];
#pragma unroll
                for (int np = 0; np < 8; np++) {
                    float b0 = sV[(ko + tig) * VST + 8 * np + g];
                    float b1 = sV[(ko + tig + 4) * VST + 8 * np + g];
                    mma_tf32(o[np], a0, a1, a2, a3, b0, b1);
                }
            }
            __syncwarp();   // sP reads done before next iteration overwrites
        }

        // ---- epilogue: exchange stream-2, combine, RMS, store ----
        __syncthreads();   // all reads of sK done (scratch aliases sK1)
        if (st == 1) {
            float fA = lam / lA, fB = lam / lB;
#pragma unroll
            for (int n = 0; n < 8; n++) {
                int c0 = 8 * n + 2 * tig;
                *(float2*)&scratch[rAl * 66 + c0]       = make_float2(o[n][0] * fA, o[n][1] * fA);
                *(float2*)&scratch[(rAl + 8) * 66 + c0] = make_float2(o[n][2] * fB, o[n][3] * fB);
            }
        }
        __syncthreads();
        if (st == 0) {
            float fA = 1.f / lA, fB = 1.f / lB;
            float oA[16], oB[16];
            float ssA = 0.f, ssB = 0.f;
#pragma unroll
            for (int n = 0; n < 8; n++) {
                int c0 = 8 * n + 2 * tig;
                float2 sA2 = *(float2*)&scratch[rAl * 66 + c0];
                float2 sB2 = *(float2*)&scratch[(rAl + 8) * 66 + c0];
                oA[2 * n]     = o[n][0] * fA - sA2.x;
                oA[2 * n + 1] = o[n][1] * fA - sA2.y;
                oB[2 * n]     = o[n][2] * fB - sB2.x;
                oB[2 * n + 1] = o[n][3] * fB - sB2.y;
                ssA += oA[2 * n] * oA[2 * n] + oA[2 * n + 1] * oA[2 * n + 1];
                ssB += oB[2 * n] * oB[2 * n] + oB[2 * n + 1] * oB[2 * n + 1];
            }
            ssA += __shfl_xor_sync(0xffffffffu, ssA, 1);
            ssA += __shfl_xor_sync(0xffffffffu, ssA, 2);
            ssB += __shfl_xor_sync(0xffffffffu, ssB, 1);
            ssB += __shfl_xor_sync(0xffffffffu, ssB, 2);
            float rnA = rsqrtf(ssA * (1.f / 64.f) + 1e-6f);
            float rnB = rsqrtf(ssB * (1.f / 64.f) + 1e-6f);

            size_t rowA = (size_t)(b * S_ + qt * 64 + rAl) * D_ + h * 64;
            size_t rowB = rowA + (size_t)8 * D_;
#pragma unroll
            for (int n = 0; n < 8; n++) {
                int c0 = 8 * n + 2 * tig;
                float2 hw2 = *(const float2*)&head_w[h * 64 + c0];
                *(float2*)&g_y[rowA + c0] =
                    make_float2(oA[2 * n] * rnA * hw2.x * 0.8f, oA[2 * n + 1] * rnA * hw2.y * 0.8f);
                *(float2*)&g_y[rowB + c0] =
                    make_float2(oB[2 * n] * rnB * hw2.x * 0.8f, oB[2 * n + 1] * rnB * hw2.y * 0.8f);
            }
        }
        __syncthreads();   // scratch reuse next rep / Q reload
    }
}

// ---------------- launch ----------------
extern "C" void kernel_launch(void* const* d_in, const int* in_sizes, int n_in,
                              void* d_out, int out_size) {
    const float* x   = (const float*)d_in[0];
    const float* Wq  = (const float*)d_in[1];
    const float* bq  = (const float*)d_in[2];
    const float* Wk  = (const float*)d_in[3];
    const float* bk  = (const float*)d_in[4];
    const float* Wv  = (const float*)d_in[5];
    const float* bv  = (const float*)d_in[6];
    const float* Wo  = (const float*)d_in[7];
    const float* bo  = (const float*)d_in[8];
    const float* hw  = (const float*)d_in[9];
    const float* lq1 = (const float*)d_in[10];
    const float* lk1 = (const float*)d_in[11];
    const float* lq2 = (const float*)d_in[12];
    const float* lk2 = (const float*)d_in[13];
    float* out = (float*)d_out;

    float *pq, *pk, *pv, *py;
    cudaGetSymbolAddress((void**)&pq, g_q);
    cudaGetSymbolAddress((void**)&pk, g_k);
    cudaGetSymbolAddress((void**)&pv, g_v);
    cudaGetSymbolAddress((void**)&py, g_y);

    const int smem_attn = (6 * 64 * QST + 64 * VST) * (int)sizeof(float);  // 122880 B
    cudaFuncSetAttribute(attn_kernel, cudaFuncAttributeMaxDynamicSharedMemorySize, smem_attn);

    dim3 blk(256);
    rope_table_kernel<<<S_, 32>>>();
    gemm_nt_bias<<<dim3(NQ_ / 128, MS_ / 128), blk>>>(x, Wq, bq, pq, MS_, NQ_, D_);
    gemm_nt_bias<<<dim3(NQ_ / 128, MS_ / 128), blk>>>(x, Wk, bk, pk, MS_, NQ_, D_);
    gemm_nt_bias<<<dim3(D_ / 128, MS_ / 128), blk>>>(x, Wv, bv, pv, MS_, D_, D_);
    rope_kernel<<<MS_, 512>>>();
    lam_kernel<<<1, 32>>>(lq1, lk1, lq2, lk2);
    attn_kernel<<<dim3(16, H_, B_), blk, smem_attn>>>(hw);
    gemm_nt_bias<<<dim3(D_ / 128, MS_ / 128), blk>>>(py, Wo, bo, out, MS_, D_, D_);
}

// round 14
// speedup vs baseline: 8.1288x; 1.8603x over previous
#include <cuda_runtime.h>
#include <math.h>
#include <stdint.h>

#define B_   2
#define S_   2048
#define D_   1024
#define H_   16
#define MS_  (B_*S_)        // 4096 rows
#define NQ_  (2*D_)         // 2048
#define QST  68             // attn Q/K/P row stride (floats)
#define VST  72             // attn V row stride (floats)
#define GST  36             // gemm smem row stride (floats)
#define LAMBDA_INIT 0.2f
#define SCALE_QK 0.125f

// ---------------- scratch ----------------
__device__ float g_q[MS_ * NQ_];
__device__ float g_k[MS_ * NQ_];
__device__ float g_v[MS_ * D_];
__device__ float g_y[MS_ * D_];
__device__ float g_lam[H_];
__device__ float g_cos[S_ * 32];
__device__ float g_sin[S_ * 32];

// ---------------- helpers ----------------
__device__ __forceinline__ float to_tf32(float x) {
    uint32_t u;
    asm("cvt.rna.tf32.f32 %0, %1;\n" : "=r"(u) : "f"(x));
    return __uint_as_float(u);
}
__device__ __forceinline__ void mma_tf32(float* d, float a0, float a1, float a2, float a3,
                                         float b0, float b1) {
    asm volatile("mma.sync.aligned.m16n8k8.row.col.f32.tf32.tf32.f32 "
                 "{%0,%1,%2,%3},{%4,%5,%6,%7},{%8,%9},{%0,%1,%2,%3};\n"
                 : "+f"(d[0]), "+f"(d[1]), "+f"(d[2]), "+f"(d[3])
                 : "r"(__float_as_uint(a0)), "r"(__float_as_uint(a1)),
                   "r"(__float_as_uint(a2)), "r"(__float_as_uint(a3)),
                   "r"(__float_as_uint(b0)), "r"(__float_as_uint(b1)));
}

// ---------------- RoPE table ----------------
__global__ void rope_table_kernel() {
    const int s = blockIdx.x;
    const int d = threadIdx.x;
    float invf = (float)pow(10000.0, -(double)d / 32.0);
    float angf = (float)s * invf;
    double cd, sd;
    sincos((double)angf, &cd, &sd);
    g_cos[s * 32 + d] = (float)cd;
    g_sin[s * 32 + d] = -(float)sd;   // flipped rotation (verified)
}

// ---------------- RoPE apply, fp32 in place ----------------
__global__ void rope_kernel() {
    const int r = blockIdx.x;
    const int h = threadIdx.x >> 5;
    const int d = threadIdx.x & 31;
    const int s = r & (S_ - 1);
    const float c  = g_cos[s * 32 + d];
    const float sn = g_sin[s * 32 + d];
    const size_t base = (size_t)r * NQ_ + h * 128;
    {
        float x1 = g_q[base + d], x2 = g_q[base + d + 32];
        g_q[base + d]      = x1 * c - x2 * sn;
        g_q[base + d + 32] = x1 * sn + x2 * c;
    }
    {
        float x1 = g_q[base + 64 + d], x2 = g_q[base + 96 + d];
        g_q[base + 64 + d] = x1 * c - x2 * sn;
        g_q[base + 96 + d] = x1 * sn + x2 * c;
    }
    {
        float x1 = g_k[base + d], x2 = g_k[base + d + 32];
        g_k[base + d]      = x1 * c - x2 * sn;
        g_k[base + d + 32] = x1 * sn + x2 * c;
    }
    {
        float x1 = g_k[base + 64 + d], x2 = g_k[base + 96 + d];
        g_k[base + 64 + d] = x1 * c - x2 * sn;
        g_k[base + 96 + d] = x1 * sn + x2 * c;
    }
}

// ---------------- TF32 tensor-core GEMM: C = A @ W^T + bias ----------------
// 128x128 block tile, K-tile 32, 256 thr (8 warps, 2m x 4n), warp tile 64x32.
// Fragment mapping identical to the attention kernel (proven R13).
__global__ __launch_bounds__(256, 1) void gemm_tf32(const float* __restrict__ A,
                                                    const float* __restrict__ W,
                                                    const float* __restrict__ bias,
                                                    float* __restrict__ C,
                                                    int M, int N, int K) {
    extern __shared__ __align__(16) float gsm[];
    float* sA = gsm;                        // 2 x 128*GST
    float* sW = gsm + 2 * 128 * GST;        // 2 x 128*GST

    const int tid = threadIdx.x;
    const int w = tid >> 5, lane = tid & 31;
    const int wm = w >> 2, wn = w & 3;
    const int g = lane >> 2, tig = lane & 3;
    const int row0 = blockIdx.y * 128;
    const int col0 = blockIdx.x * 128;

    const int lr = tid >> 3;            // 0..31? no: 256/8=32 -> need 128 rows /4 iters
    const int lc = (tid & 7) << 2;      // 0,4,..28

    float acc[4][4][4];
#pragma unroll
    for (int mt = 0; mt < 4; mt++)
#pragma unroll
        for (int nt = 0; nt < 4; nt++)
#pragma unroll
            for (int i = 0; i < 4; i++) acc[mt][nt][i] = 0.f;

    const int T = K / 32;

    // preload tile 0
#pragma unroll
    for (int i = 0; i < 4; i++) {
        int r = lr + i * 32;
        float4 av = *(const float4*)&A[(size_t)(row0 + r) * K + lc];
        float4 wv = *(const float4*)&W[(size_t)(col0 + r) * K + lc];
        float* da = sA + r * GST + lc;
        float* dw = sW + r * GST + lc;
        da[0] = to_tf32(av.x); da[1] = to_tf32(av.y); da[2] = to_tf32(av.z); da[3] = to_tf32(av.w);
        dw[0] = to_tf32(wv.x); dw[1] = to_tf32(wv.y); dw[2] = to_tf32(wv.z); dw[3] = to_tf32(wv.w);
    }
    __syncthreads();

    for (int t = 0; t < T; t++) {
        const int cur = t & 1;
        float4 av[4], wv[4];
        if (t + 1 < T) {
            const int k0 = (t + 1) * 32;
#pragma unroll
            for (int i = 0; i < 4; i++) {
                int r = lr + i * 32;
                av[i] = *(const float4*)&A[(size_t)(row0 + r) * K + k0 + lc];
                wv[i] = *(const float4*)&W[(size_t)(col0 + r) * K + k0 + lc];
            }
        }

        const float* Ab = sA + cur * 128 * GST + (wm * 64 + g) * GST + tig;
        const float* Wb = sW + cur * 128 * GST + (wn * 32 + g) * GST + tig;
#pragma unroll
        for (int k8 = 0; k8 < 4; k8++) {
            const int ko = k8 * 8;
            float a[4][4];
#pragma unroll
            for (int mt = 0; mt < 4; mt++) {
                a[mt][0] = Ab[(mt * 16) * GST + ko];
                a[mt][1] = Ab[(mt * 16 + 8) * GST + ko];
                a[mt][2] = Ab[(mt * 16) * GST + ko + 4];
                a[mt][3] = Ab[(mt * 16 + 8) * GST + ko + 4];
            }
#pragma unroll
            for (int nt = 0; nt < 4; nt++) {
                float b0 = Wb[(nt * 8) * GST + ko];
                float b1 = Wb[(nt * 8) * GST + ko + 4];
#pragma unroll
                for (int mt = 0; mt < 4; mt++)
                    mma_tf32(acc[mt][nt], a[mt][0], a[mt][1], a[mt][2], a[mt][3], b0, b1);
            }
        }

        if (t + 1 < T) {
            const int nxt = 1 - cur;
            float* baseA = sA + nxt * 128 * GST;
            float* baseW = sW + nxt * 128 * GST;
            __syncthreads();
#pragma unroll
            for (int i = 0; i < 4; i++) {
                int r = lr + i * 32;
                float* da = baseA + r * GST + lc;
                float* dw = baseW + r * GST + lc;
                da[0] = to_tf32(av[i].x); da[1] = to_tf32(av[i].y);
                da[2] = to_tf32(av[i].z); da[3] = to_tf32(av[i].w);
                dw[0] = to_tf32(wv[i].x); dw[1] = to_tf32(wv[i].y);
                dw[2] = to_tf32(wv[i].z); dw[3] = to_tf32(wv[i].w);
            }
            __syncthreads();
        }
    }

    // epilogue: bias + store
#pragma unroll
    for (int nt = 0; nt < 4; nt++) {
        const int col = col0 + wn * 32 + nt * 8 + 2 * tig;
        float2 bb = *(const float2*)&bias[col];
#pragma unroll
        for (int mt = 0; mt < 4; mt++) {
            const int rowA = row0 + wm * 64 + mt * 16 + g;
            *(float2*)&C[(size_t)rowA * N + col] =
                make_float2(acc[mt][nt][0] + bb.x, acc[mt][nt][1] + bb.y);
            *(float2*)&C[(size_t)(rowA + 8) * N + col] =
                make_float2(acc[mt][nt][2] + bb.x, acc[mt][nt][3] + bb.y);
        }
    }
}

// ---------------- lambda ----------------
__global__ void lam_kernel(const float* __restrict__ lq1, const float* __restrict__ lk1,
                           const float* __restrict__ lq2, const float* __restrict__ lk2) {
    int h = threadIdx.x;
    if (h < H_) {
        float d1 = 0.f, d2 = 0.f;
        for (int i = 0; i < 64; i++) {
            d1 += lq1[h * 64 + i] * lk1[h * 64 + i];
            d2 += lq2[h * 64 + i] * lk2[h * 64 + i];
        }
        g_lam[h] = LAMBDA_INIT + expf(d1) - expf(d2);
    }
}

// ---------------- TF32 tensor-core dual-stream causal attention (R13, passing) ----
__global__ __launch_bounds__(256, 1) void attn_kernel(const float* __restrict__ head_w) {
    extern __shared__ __align__(16) float smem[];
    float* sQ1 = smem;
    float* sQ2 = sQ1 + 64 * QST;
    float* sK1 = sQ2 + 64 * QST;
    float* sK2 = sK1 + 64 * QST;
    float* sP1 = sK2 + 64 * QST;
    float* sP2 = sP1 + 64 * QST;
    float* sV  = sP2 + 64 * QST;
    float* scratch = sK1;

    const int p = blockIdx.x, h = blockIdx.y, b = blockIdx.z;
    const int tid = threadIdx.x;
    const int w = tid >> 5, lane = tid & 31;
    const int st = w >> 2, wr = w & 3;
    const int g = lane >> 2, tig = lane & 3;
    const float lam = g_lam[h];

    float* sQ  = st ? sQ2 : sQ1;
    float* sKs = st ? sK2 : sK1;
    float* sP  = st ? sP2 : sP1;
    const int rAl = 16 * wr + g;

    for (int rep = 0; rep < 2; rep++) {
        const int qt = (rep == 0) ? p : (31 - p);

#pragma unroll
        for (int i = 0; i < 8; i++) {
            int idx = tid + i * 256;
            int strm = idx >> 10;
            int r = (idx >> 4) & 63;
            int c4 = idx & 15;
            float4 v = *(const float4*)&g_q[(size_t)(b * S_ + qt * 64 + r) * NQ_ + h * 128 + strm * 64 + c4 * 4];
            float* dst = (strm ? sQ2 : sQ1) + r * QST + c4 * 4;
            dst[0] = to_tf32(v.x * SCALE_QK);
            dst[1] = to_tf32(v.y * SCALE_QK);
            dst[2] = to_tf32(v.z * SCALE_QK);
            dst[3] = to_tf32(v.w * SCALE_QK);
        }

        float o[8][4];
#pragma unroll
        for (int n = 0; n < 8; n++) { o[n][0] = o[n][1] = o[n][2] = o[n][3] = 0.f; }
        float lA = 0.f, lB = 0.f;

        for (int kt = 0; kt <= qt; kt++) {
            __syncthreads();
#pragma unroll
            for (int i = 0; i < 12; i++) {
                int idx = tid + i * 256;
                if (idx < 2048) {
                    int strm = idx >> 10;
                    int r = (idx >> 4) & 63;
                    int c4 = idx & 15;
                    float4 v = *(const float4*)&g_k[(size_t)(b * S_ + kt * 64 + r) * NQ_ + h * 128 + strm * 64 + c4 * 4];
                    float* dst = (strm ? sK2 : sK1) + r * QST + c4 * 4;
                    dst[0] = to_tf32(v.x); dst[1] = to_tf32(v.y);
                    dst[2] = to_tf32(v.z); dst[3] = to_tf32(v.w);
                } else {
                    int j = idx - 2048;
                    int r = j >> 4;
                    int c4 = j & 15;
                    float4 v = *(const float4*)&g_v[(size_t)(b * S_ + kt * 64 + r) * D_ + h * 64 + c4 * 4];
                    float* dst = sV + r * VST + c4 * 4;
                    dst[0] = to_tf32(v.x); dst[1] = to_tf32(v.y);
                    dst[2] = to_tf32(v.z); dst[3] = to_tf32(v.w);
                }
            }
            __syncthreads();

            float s[8][4];
#pragma unroll
            for (int n = 0; n < 8; n++) { s[n][0] = s[n][1] = s[n][2] = s[n][3] = 0.f; }
            const float* Qb = sQ + rAl * QST + tig;
            const float* Kb = sKs + g * QST + tig;
#pragma unroll
            for (int k8 = 0; k8 < 8; k8++) {
                const int ko = 8 * k8;
                float a0 = Qb[ko];
                float a1 = Qb[8 * QST + ko];
                float a2 = Qb[ko + 4];
                float a3 = Qb[8 * QST + ko + 4];
#pragma unroll
                for (int np = 0; np < 8; np++) {
                    float b0 = Kb[np * 8 * QST + ko];
                    float b1 = Kb[np * 8 * QST + ko + 4];
                    mma_tf32(s[np], a0, a1, a2, a3, b0, b1);
                }
            }

            const bool diag = (kt == qt);
            float sumA = 0.f, sumB = 0.f;
#pragma unroll
            for (int n = 0; n < 8; n++) {
                int c0 = 8 * n + 2 * tig;
                float p00, p01, p10, p11;
                if (diag) {
                    p00 = (c0     > rAl)     ? 0.f : __expf(s[n][0]);
                    p01 = (c0 + 1 > rAl)     ? 0.f : __expf(s[n][1]);
                    p10 = (c0     > rAl + 8) ? 0.f : __expf(s[n][2]);
                    p11 = (c0 + 1 > rAl + 8) ? 0.f : __expf(s[n][3]);
                } else {
                    p00 = __expf(s[n][0]); p01 = __expf(s[n][1]);
                    p10 = __expf(s[n][2]); p11 = __expf(s[n][3]);
                }
                sumA += p00 + p01;
                sumB += p10 + p11;
                *(float2*)&sP[rAl * QST + c0]       = make_float2(to_tf32(p00), to_tf32(p01));
                *(float2*)&sP[(rAl + 8) * QST + c0] = make_float2(to_tf32(p10), to_tf32(p11));
            }
            sumA += __shfl_xor_sync(0xffffffffu, sumA, 1);
            sumA += __shfl_xor_sync(0xffffffffu, sumA, 2);
            sumB += __shfl_xor_sync(0xffffffffu, sumB, 1);
            sumB += __shfl_xor_sync(0xffffffffu, sumB, 2);
            lA += sumA;
            lB += sumB;
            __syncwarp();

            const float* Pb = sP + rAl * QST + tig;
#pragma unroll
            for (int k8 = 0; k8 < 8; k8++) {
                const int ko = 8 * k8;
                float a0 = Pb[ko];
                float a1 = Pb[8 * QST + ko];
                float a2 = Pb[ko + 4];
                float a3 = Pb[8 * QST + ko + 4];
#pragma unroll
                for (int np = 0; np < 8; np++) {
                    float b0 = sV[(ko + tig) * VST + 8 * np + g];
                    float b1 = sV[(ko + tig + 4) * VST + 8 * np + g];
                    mma_tf32(o[np], a0, a1, a2, a3, b0, b1);
                }
            }
            __syncwarp();
        }

        __syncthreads();
        if (st == 1) {
            float fA = lam / lA, fB = lam / lB;
#pragma unroll
            for (int n = 0; n < 8; n++) {
                int c0 = 8 * n + 2 * tig;
                *(float2*)&scratch[rAl * 66 + c0]       = make_float2(o[n][0] * fA, o[n][1] * fA);
                *(float2*)&scratch[(rAl + 8) * 66 + c0] = make_float2(o[n][2] * fB, o[n][3] * fB);
            }
        }
        __syncthreads();
        if (st == 0) {
            float fA = 1.f / lA, fB = 1.f / lB;
            float oA[16], oB[16];
            float ssA = 0.f, ssB = 0.f;
#pragma unroll
            for (int n = 0; n < 8; n++) {
                int c0 = 8 * n + 2 * tig;
                float2 sA2 = *(float2*)&scratch[rAl * 66 + c0];
                float2 sB2 = *(float2*)&scratch[(rAl + 8) * 66 + c0];
                oA[2 * n]     = o[n][0] * fA - sA2.x;
                oA[2 * n + 1] = o[n][1] * fA - sA2.y;
                oB[2 * n]     = o[n][2] * fB - sB2.x;
                oB[2 * n + 1] = o[n][3] * fB - sB2.y;
                ssA += oA[2 * n] * oA[2 * n] + oA[2 * n + 1] * oA[2 * n + 1];
                ssB += oB[2 * n] * oB[2 * n] + oB[2 * n + 1] * oB[2 * n + 1];
            }
            ssA += __shfl_xor_sync(0xffffffffu, ssA, 1);
            ssA += __shfl_xor_sync(0xffffffffu, ssA, 2);
            ssB += __shfl_xor_sync(0xffffffffu, ssB, 1);
            ssB += __shfl_xor_sync(0xffffffffu, ssB, 2);
            float rnA = rsqrtf(ssA * (1.f / 64.f) + 1e-6f);
            float rnB = rsqrtf(ssB * (1.f / 64.f) + 1e-6f);

            size_t rowA = (size_t)(b * S_ + qt * 64 + rAl) * D_ + h * 64;
            size_t rowB = rowA + (size_t)8 * D_;
#pragma unroll
            for (int n = 0; n < 8; n++) {
                int c0 = 8 * n + 2 * tig;
                float2 hw2 = *(const float2*)&head_w[h * 64 + c0];
                *(float2*)&g_y[rowA + c0] =
                    make_float2(oA[2 * n] * rnA * hw2.x * 0.8f, oA[2 * n + 1] * rnA * hw2.y * 0.8f);
                *(float2*)&g_y[rowB + c0] =
                    make_float2(oB[2 * n] * rnB * hw2.x * 0.8f, oB[2 * n + 1] * rnB * hw2.y * 0.8f);
            }
        }
        __syncthreads();
    }
}

// ---------------- launch ----------------
extern "C" void kernel_launch(void* const* d_in, const int* in_sizes, int n_in,
                              void* d_out, int out_size) {
    const float* x   = (const float*)d_in[0];
    const float* Wq  = (const float*)d_in[1];
    const float* bq  = (const float*)d_in[2];
    const float* Wk  = (const float*)d_in[3];
    const float* bk  = (const float*)d_in[4];
    const float* Wv  = (const float*)d_in[5];
    const float* bv  = (const float*)d_in[6];
    const float* Wo  = (const float*)d_in[7];
    const float* bo  = (const float*)d_in[8];
    const float* hw  = (const float*)d_in[9];
    const float* lq1 = (const float*)d_in[10];
    const float* lk1 = (const float*)d_in[11];
    const float* lq2 = (const float*)d_in[12];
    const float* lk2 = (const float*)d_in[13];
    float* out = (float*)d_out;

    float *pq, *pk, *pv, *py;
    cudaGetSymbolAddress((void**)&pq, g_q);
    cudaGetSymbolAddress((void**)&pk, g_k);
    cudaGetSymbolAddress((void**)&pv, g_v);
    cudaGetSymbolAddress((void**)&py, g_y);

    const int smem_attn = (6 * 64 * QST + 64 * VST) * (int)sizeof(float);   // 122880 B
    cudaFuncSetAttribute(attn_kernel, cudaFuncAttributeMaxDynamicSharedMemorySize, smem_attn);
    const int smem_gemm = 4 * 128 * GST * (int)sizeof(float);               // 73728 B
    cudaFuncSetAttribute(gemm_tf32, cudaFuncAttributeMaxDynamicSharedMemorySize, smem_gemm);

    dim3 blk(256);
    rope_table_kernel<<<S_, 32>>>();
    gemm_tf32<<<dim3(NQ_ / 128, MS_ / 128), blk, smem_gemm>>>(x, Wq, bq, pq, MS_, NQ_, D_);
    gemm_tf32<<<dim3(NQ_ / 128, MS_ / 128), blk, smem_gemm>>>(x, Wk, bk, pk, MS_, NQ_, D_);
    gemm_tf32<<<dim3(D_ / 128, MS_ / 128), blk, smem_gemm>>>(x, Wv, bv, pv, MS_, D_, D_);
    rope_kernel<<<MS_, 512>>>();
    lam_kernel<<<1, 32>>>(lq1, lk1, lq2, lk2);
    attn_kernel<<<dim3(16, H_, B_), blk, smem_attn>>>(hw);
    gemm_tf32<<<dim3(D_ / 128, MS_ / 128), blk, smem_gemm>>>(py, Wo, bo, out, MS_, D_, D_);
}